// round 1
// baseline (speedup 1.0000x reference)
#include <cuda_runtime.h>

#define NODES_MAX 50048
#define DIM 128

// Scratch (static __device__ arrays per the allocation rules)
__device__ float g_deg[NODES_MAX];                       // in-degree -> 1/max(deg,1)
__device__ float g_agg[(size_t)NODES_MAX * DIM];         // scatter-sum buffer
__device__ float g_h[(size_t)NODES_MAX * DIM];           // hidden activations

// ---------------- packed f32x2 helpers (Blackwell) ----------------
__device__ __forceinline__ unsigned long long pack2(float x, float y) {
    unsigned long long r;
    asm("mov.b64 %0, {%1, %2};" : "=l"(r) : "f"(x), "f"(y));
    return r;
}
__device__ __forceinline__ void fma2(unsigned long long& d,
                                     unsigned long long a,
                                     unsigned long long b) {
    asm("fma.rn.f32x2 %0, %1, %2, %0;" : "+l"(d) : "l"(a), "l"(b));
}
__device__ __forceinline__ void unpack2(unsigned long long v, float& x, float& y) {
    asm("mov.b64 {%0, %1}, %2;" : "=f"(x), "=f"(y) : "l"(v));
}

// ---------------- utility kernels ----------------
__global__ void fill_zero_kernel(float* __restrict__ p, int n_float4) {
    int i = blockIdx.x * blockDim.x + threadIdx.x;
    if (i < n_float4) reinterpret_cast<float4*>(p)[i] = make_float4(0.f, 0.f, 0.f, 0.f);
}

__global__ void deg_kernel(const int* __restrict__ dst, float* __restrict__ deg, int E) {
    int e = blockIdx.x * blockDim.x + threadIdx.x;
    if (e < E) atomicAdd(&deg[dst[e]], 1.0f);
}

__global__ void inv_kernel(float* __restrict__ deg, int n) {
    int i = blockIdx.x * blockDim.x + threadIdx.x;
    if (i < n) deg[i] = 1.0f / fmaxf(deg[i], 1.0f);
}

// One warp per edge: lane handles 4 contiguous floats. src/dst loads are
// warp-uniform; feature reads and atomics are fully coalesced / spread.
__global__ void scatter_kernel(const float* __restrict__ feat,
                               const int* __restrict__ src,
                               const int* __restrict__ dst,
                               float* __restrict__ agg, int E) {
    long long t = (long long)blockIdx.x * blockDim.x + threadIdx.x;
    int e = (int)(t >> 5);
    if (e >= E) return;
    int lane = (int)(t & 31);
    int s = __ldg(src + e);
    int d = __ldg(dst + e);
    float4 v = *reinterpret_cast<const float4*>(feat + (size_t)s * DIM + lane * 4);
    float* p = agg + (size_t)d * DIM + lane * 4;
    atomicAdd(p + 0, v.x);
    atomicAdd(p + 1, v.y);
    atomicAdd(p + 2, v.z);
    atomicAdd(p + 3, v.w);
}

// ---------------- fused SAGE layer ----------------
// out[r,:] = X[r,:] @ Ws + b + (AGG[r,:] * invdeg[r]) @ Wn   (+ optional ReLU)
// Tile: 32 rows x F_OUT cols per block, 256 threads, packed f32x2 FMAs.
template <int F_OUT, bool RELU>
__global__ void __launch_bounds__(256)
layer_kernel(const float* __restrict__ X, const float* __restrict__ AGG,
             const float* __restrict__ invdeg,
             const float* __restrict__ Ws, const float* __restrict__ b,
             const float* __restrict__ Wn, float* __restrict__ out, int n) {
    constexpr int TM  = 32;
    constexpr int CG  = F_OUT / 4;     // column groups of 4
    constexpr int TPC = 256 / CG;      // threads stacked along rows
    constexpr int RPT = TM / TPC;      // rows per thread

    __shared__ float As[TM][DIM];
    __shared__ float Gs[TM][DIM];

    const int t = threadIdx.x;
    const int block_row = blockIdx.x * TM;

    // Load X and AGG tiles (AGG scaled by 1/deg on the way in)
#pragma unroll
    for (int it = 0; it < (TM * DIM / 4) / 256; ++it) {
        int idx = t + it * 256;          // float4 slot
        int r = idx / (DIM / 4);
        int c = (idx % (DIM / 4)) * 4;
        int gr = block_row + r;
        float4 xv = make_float4(0.f, 0.f, 0.f, 0.f);
        float4 gv = xv;
        if (gr < n) {
            xv = *reinterpret_cast<const float4*>(X + (size_t)gr * DIM + c);
            gv = *reinterpret_cast<const float4*>(AGG + (size_t)gr * DIM + c);
            float s = __ldg(invdeg + gr);
            gv.x *= s; gv.y *= s; gv.z *= s; gv.w *= s;
        }
        *reinterpret_cast<float4*>(&As[r][c]) = xv;
        *reinterpret_cast<float4*>(&Gs[r][c]) = gv;
    }
    __syncthreads();

    const int tc = t % CG;   // column group -> cols [tc*4, tc*4+4)
    const int tr = t / CG;   // base row

    unsigned long long acc[RPT][2];
#pragma unroll
    for (int j = 0; j < RPT; ++j) { acc[j][0] = pack2(0.f, 0.f); acc[j][1] = pack2(0.f, 0.f); }

#pragma unroll 4
    for (int k = 0; k < DIM; ++k) {
        float4 ws = __ldg(reinterpret_cast<const float4*>(Ws + (size_t)k * F_OUT) + tc);
        float4 wn = __ldg(reinterpret_cast<const float4*>(Wn + (size_t)k * F_OUT) + tc);
        unsigned long long ws01 = pack2(ws.x, ws.y), ws23 = pack2(ws.z, ws.w);
        unsigned long long wn01 = pack2(wn.x, wn.y), wn23 = pack2(wn.z, wn.w);
#pragma unroll
        for (int j = 0; j < RPT; ++j) {
            int r = tr + j * TPC;
            float a = As[r][k];
            float g = Gs[r][k];
            unsigned long long a2 = pack2(a, a);
            unsigned long long g2 = pack2(g, g);
            fma2(acc[j][0], a2, ws01);
            fma2(acc[j][1], a2, ws23);
            fma2(acc[j][0], g2, wn01);
            fma2(acc[j][1], g2, wn23);
        }
    }

    float4 bv = __ldg(reinterpret_cast<const float4*>(b) + tc);
#pragma unroll
    for (int j = 0; j < RPT; ++j) {
        int gr = block_row + tr + j * TPC;
        if (gr < n) {
            float o0, o1, o2, o3;
            unpack2(acc[j][0], o0, o1);
            unpack2(acc[j][1], o2, o3);
            o0 += bv.x; o1 += bv.y; o2 += bv.z; o3 += bv.w;
            if (RELU) {
                o0 = fmaxf(o0, 0.f); o1 = fmaxf(o1, 0.f);
                o2 = fmaxf(o2, 0.f); o3 = fmaxf(o3, 0.f);
            }
            *reinterpret_cast<float4*>(out + (size_t)gr * F_OUT + tc * 4) =
                make_float4(o0, o1, o2, o3);
        }
    }
}

// ---------------- launch ----------------
extern "C" void kernel_launch(void* const* d_in, const int* in_sizes, int n_in,
                              void* d_out, int out_size) {
    const float* x   = (const float*)d_in[0];
    const int*   src = (const int*)d_in[1];
    const int*   dst = (const int*)d_in[2];
    const float* Ws1 = (const float*)d_in[3];
    const float* b1  = (const float*)d_in[4];
    const float* Wn1 = (const float*)d_in[5];
    const float* Ws2 = (const float*)d_in[6];
    const float* b2  = (const float*)d_in[7];
    const float* Wn2 = (const float*)d_in[8];
    const float* Ws3 = (const float*)d_in[9];
    const float* b3  = (const float*)d_in[10];
    const float* Wn3 = (const float*)d_in[11];

    const int N = in_sizes[0] / DIM;
    const int E = in_sizes[1];
    float* out = (float*)d_out;

    float *deg, *agg, *h;
    cudaGetSymbolAddress((void**)&deg, g_deg);
    cudaGetSymbolAddress((void**)&agg, g_agg);
    cudaGetSymbolAddress((void**)&h,   g_h);

    const int feat4 = (N * DIM) / 4;
    const int fill_blocks = (feat4 + 255) / 256;
    const long long scat_threads = (long long)E * 32;
    const int scat_blocks = (int)((scat_threads + 255) / 256);
    const int layer_blocks = (N + 31) / 32;

    // degree -> 1/max(deg,1)  (computed once, reused by all layers)
    fill_zero_kernel<<<(N / 4 + 255) / 256, 256>>>(deg, N / 4);
    deg_kernel<<<(E + 255) / 256, 256>>>(dst, deg, E);
    inv_kernel<<<(N + 255) / 256, 256>>>(deg, N);

    // Layer 1: x -> h
    fill_zero_kernel<<<fill_blocks, 256>>>(agg, feat4);
    scatter_kernel<<<scat_blocks, 256>>>(x, src, dst, agg, E);
    layer_kernel<128, true><<<layer_blocks, 256>>>(x, agg, deg, Ws1, b1, Wn1, h, N);

    // Layer 2: h -> h (in-place is safe: each block only reads/writes its own rows,
    // with reads staged to smem before any write)
    fill_zero_kernel<<<fill_blocks, 256>>>(agg, feat4);
    scatter_kernel<<<scat_blocks, 256>>>(h, src, dst, agg, E);
    layer_kernel<128, true><<<layer_blocks, 256>>>(h, agg, deg, Ws2, b2, Wn2, h, N);

    // Layer 3: h -> out (mean_agg commutes with the linear map, so
    // agg-then-matmul is exact-equivalent to the reference's lin_before_mp)
    fill_zero_kernel<<<fill_blocks, 256>>>(agg, feat4);
    scatter_kernel<<<scat_blocks, 256>>>(h, src, dst, agg, E);
    layer_kernel<64, false><<<layer_blocks, 256>>>(h, agg, deg, Ws3, b3, Wn3, out, N);
}

// round 2
// speedup vs baseline: 2.2416x; 2.2416x over previous
#include <cuda_runtime.h>

#define NODES_MAX 50048
#define EDGES_MAX 800000
#define DIM 128

// ---------------- device scratch (allocation-free rule) ----------------
__device__ int   g_deg_i[NODES_MAX];
__device__ int   g_fill[NODES_MAX];
__device__ int   g_rowptr[NODES_MAX + 1];
__device__ int   g_csr[EDGES_MAX];
__device__ float g_invdeg[NODES_MAX];
__device__ float g_agg[(size_t)NODES_MAX * DIM];
__device__ float g_h[(size_t)NODES_MAX * DIM];

// ---------------- packed f32x2 helpers (Blackwell) ----------------
__device__ __forceinline__ unsigned long long pack2(float x, float y) {
    unsigned long long r;
    asm("mov.b64 %0, {%1, %2};" : "=l"(r) : "f"(x), "f"(y));
    return r;
}
__device__ __forceinline__ void fma2(unsigned long long& d,
                                     unsigned long long a,
                                     unsigned long long b) {
    asm("fma.rn.f32x2 %0, %1, %2, %0;" : "+l"(d) : "l"(a), "l"(b));
}
__device__ __forceinline__ void unpack2(unsigned long long v, float& x, float& y) {
    asm("mov.b64 {%0, %1}, %2;" : "=f"(x), "=f"(y) : "l"(v));
}

// ---------------- CSR build ----------------
__global__ void zero_int_kernel(int* __restrict__ p, int n) {
    int i = blockIdx.x * blockDim.x + threadIdx.x;
    if (i < n) p[i] = 0;
}

__global__ void deg_kernel(const int* __restrict__ dst, int* __restrict__ deg, int E) {
    int e = blockIdx.x * blockDim.x + threadIdx.x;
    if (e < E) atomicAdd(&deg[dst[e]], 1);
}

__global__ void invdeg_kernel(const int* __restrict__ deg, float* __restrict__ inv, int n) {
    int i = blockIdx.x * blockDim.x + threadIdx.x;
    if (i < n) inv[i] = 1.0f / (float)max(deg[i], 1);
}

// Single-block exclusive scan over node degrees -> rowptr (n <= ~50K: 49 tiles)
__global__ void __launch_bounds__(1024)
scan_kernel(const int* __restrict__ cnt, int* __restrict__ rowptr, int n) {
    __shared__ int s[1024];
    __shared__ int carry_s;
    const int tid = threadIdx.x;
    if (tid == 0) { carry_s = 0; rowptr[0] = 0; }
    __syncthreads();
    for (int base = 0; base < n; base += 1024) {
        int i = base + tid;
        int v = (i < n) ? cnt[i] : 0;
        s[tid] = v;
        __syncthreads();
#pragma unroll
        for (int off = 1; off < 1024; off <<= 1) {
            int t = (tid >= off) ? s[tid - off] : 0;
            __syncthreads();
            s[tid] += t;
            __syncthreads();
        }
        int carry = carry_s;
        if (i < n) rowptr[i + 1] = carry + s[tid];
        int total = s[1023];
        __syncthreads();
        if (tid == 0) carry_s = carry + total;
        __syncthreads();
    }
}

__global__ void fill_csr_kernel(const int* __restrict__ src, const int* __restrict__ dst,
                                const int* __restrict__ rowptr, int* __restrict__ fill,
                                int* __restrict__ csr, int E) {
    int e = blockIdx.x * blockDim.x + threadIdx.x;
    if (e < E) {
        int d = dst[e];
        int pos = rowptr[d] + atomicAdd(&fill[d], 1);
        csr[pos] = src[e];
    }
}

// ---------------- atomic-free mean aggregation ----------------
// One warp per node; lane owns 4 contiguous floats. Unroll-4 over in-edges for MLP.
__global__ void __launch_bounds__(256)
agg_kernel(const float* __restrict__ feat, const int* __restrict__ rowptr,
           const int* __restrict__ csr, const float* __restrict__ invdeg,
           float* __restrict__ agg, int n) {
    long long t = (long long)blockIdx.x * blockDim.x + threadIdx.x;
    int v = (int)(t >> 5);
    if (v >= n) return;
    int lane = (int)(t & 31);

    int beg = __ldg(rowptr + v);
    int end = __ldg(rowptr + v + 1);

    float ax = 0.f, ay = 0.f, az = 0.f, aw = 0.f;
    int i = beg;
    for (; i + 4 <= end; i += 4) {
        int s0 = __ldg(csr + i + 0);
        int s1 = __ldg(csr + i + 1);
        int s2 = __ldg(csr + i + 2);
        int s3 = __ldg(csr + i + 3);
        float4 f0 = *reinterpret_cast<const float4*>(feat + (size_t)s0 * DIM + lane * 4);
        float4 f1 = *reinterpret_cast<const float4*>(feat + (size_t)s1 * DIM + lane * 4);
        float4 f2 = *reinterpret_cast<const float4*>(feat + (size_t)s2 * DIM + lane * 4);
        float4 f3 = *reinterpret_cast<const float4*>(feat + (size_t)s3 * DIM + lane * 4);
        ax += (f0.x + f1.x) + (f2.x + f3.x);
        ay += (f0.y + f1.y) + (f2.y + f3.y);
        az += (f0.z + f1.z) + (f2.z + f3.z);
        aw += (f0.w + f1.w) + (f2.w + f3.w);
    }
    for (; i < end; ++i) {
        int s0 = __ldg(csr + i);
        float4 f0 = *reinterpret_cast<const float4*>(feat + (size_t)s0 * DIM + lane * 4);
        ax += f0.x; ay += f0.y; az += f0.z; aw += f0.w;
    }
    float sc = __ldg(invdeg + v);
    *reinterpret_cast<float4*>(agg + (size_t)v * DIM + lane * 4) =
        make_float4(ax * sc, ay * sc, az * sc, aw * sc);
}

// ---------------- fused SAGE layer ----------------
// out[r,:] = X[r,:] @ Ws + b + AGG[r,:] @ Wn   (+ optional ReLU); AGG pre-normalized.
template <int F_OUT, bool RELU>
__global__ void __launch_bounds__(256)
layer_kernel(const float* __restrict__ X, const float* __restrict__ AGG,
             const float* __restrict__ Ws, const float* __restrict__ b,
             const float* __restrict__ Wn, float* __restrict__ out, int n) {
    constexpr int TM  = 32;
    constexpr int CG  = F_OUT / 4;     // column groups of 4
    constexpr int TPC = 256 / CG;      // threads stacked along rows
    constexpr int RPT = TM / TPC;      // rows per thread

    __shared__ float As[TM][DIM];
    __shared__ float Gs[TM][DIM];

    const int t = threadIdx.x;
    const int block_row = blockIdx.x * TM;

#pragma unroll
    for (int it = 0; it < (TM * DIM / 4) / 256; ++it) {
        int idx = t + it * 256;
        int r = idx / (DIM / 4);
        int c = (idx % (DIM / 4)) * 4;
        int gr = block_row + r;
        float4 xv = make_float4(0.f, 0.f, 0.f, 0.f);
        float4 gv = xv;
        if (gr < n) {
            xv = *reinterpret_cast<const float4*>(X + (size_t)gr * DIM + c);
            gv = *reinterpret_cast<const float4*>(AGG + (size_t)gr * DIM + c);
        }
        *reinterpret_cast<float4*>(&As[r][c]) = xv;
        *reinterpret_cast<float4*>(&Gs[r][c]) = gv;
    }
    __syncthreads();

    const int tc = t % CG;
    const int tr = t / CG;

    unsigned long long acc[RPT][2];
#pragma unroll
    for (int j = 0; j < RPT; ++j) { acc[j][0] = pack2(0.f, 0.f); acc[j][1] = pack2(0.f, 0.f); }

#pragma unroll 4
    for (int k = 0; k < DIM; k += 2) {
        float4 ws0 = __ldg(reinterpret_cast<const float4*>(Ws + (size_t)k * F_OUT) + tc);
        float4 ws1 = __ldg(reinterpret_cast<const float4*>(Ws + (size_t)(k + 1) * F_OUT) + tc);
        float4 wn0 = __ldg(reinterpret_cast<const float4*>(Wn + (size_t)k * F_OUT) + tc);
        float4 wn1 = __ldg(reinterpret_cast<const float4*>(Wn + (size_t)(k + 1) * F_OUT) + tc);
        unsigned long long ws0_01 = pack2(ws0.x, ws0.y), ws0_23 = pack2(ws0.z, ws0.w);
        unsigned long long ws1_01 = pack2(ws1.x, ws1.y), ws1_23 = pack2(ws1.z, ws1.w);
        unsigned long long wn0_01 = pack2(wn0.x, wn0.y), wn0_23 = pack2(wn0.z, wn0.w);
        unsigned long long wn1_01 = pack2(wn1.x, wn1.y), wn1_23 = pack2(wn1.z, wn1.w);
#pragma unroll
        for (int j = 0; j < RPT; ++j) {
            int r = tr + j * TPC;
            float2 a = *reinterpret_cast<const float2*>(&As[r][k]);
            float2 g = *reinterpret_cast<const float2*>(&Gs[r][k]);
            unsigned long long a0 = pack2(a.x, a.x);
            unsigned long long a1 = pack2(a.y, a.y);
            unsigned long long g0 = pack2(g.x, g.x);
            unsigned long long g1 = pack2(g.y, g.y);
            fma2(acc[j][0], a0, ws0_01); fma2(acc[j][1], a0, ws0_23);
            fma2(acc[j][0], a1, ws1_01); fma2(acc[j][1], a1, ws1_23);
            fma2(acc[j][0], g0, wn0_01); fma2(acc[j][1], g0, wn0_23);
            fma2(acc[j][0], g1, wn1_01); fma2(acc[j][1], g1, wn1_23);
        }
    }

    float4 bv = __ldg(reinterpret_cast<const float4*>(b) + tc);
#pragma unroll
    for (int j = 0; j < RPT; ++j) {
        int gr = block_row + tr + j * TPC;
        if (gr < n) {
            float o0, o1, o2, o3;
            unpack2(acc[j][0], o0, o1);
            unpack2(acc[j][1], o2, o3);
            o0 += bv.x; o1 += bv.y; o2 += bv.z; o3 += bv.w;
            if (RELU) {
                o0 = fmaxf(o0, 0.f); o1 = fmaxf(o1, 0.f);
                o2 = fmaxf(o2, 0.f); o3 = fmaxf(o3, 0.f);
            }
            *reinterpret_cast<float4*>(out + (size_t)gr * F_OUT + tc * 4) =
                make_float4(o0, o1, o2, o3);
        }
    }
}

// ---------------- launch ----------------
extern "C" void kernel_launch(void* const* d_in, const int* in_sizes, int n_in,
                              void* d_out, int out_size) {
    const float* x   = (const float*)d_in[0];
    const int*   src = (const int*)d_in[1];
    const int*   dst = (const int*)d_in[2];
    const float* Ws1 = (const float*)d_in[3];
    const float* b1  = (const float*)d_in[4];
    const float* Wn1 = (const float*)d_in[5];
    const float* Ws2 = (const float*)d_in[6];
    const float* b2  = (const float*)d_in[7];
    const float* Wn2 = (const float*)d_in[8];
    const float* Ws3 = (const float*)d_in[9];
    const float* b3  = (const float*)d_in[10];
    const float* Wn3 = (const float*)d_in[11];

    const int N = in_sizes[0] / DIM;
    const int E = in_sizes[1];
    float* out = (float*)d_out;

    int *deg_i, *fill, *rowptr, *csr;
    float *invdeg, *agg, *h;
    cudaGetSymbolAddress((void**)&deg_i,  g_deg_i);
    cudaGetSymbolAddress((void**)&fill,   g_fill);
    cudaGetSymbolAddress((void**)&rowptr, g_rowptr);
    cudaGetSymbolAddress((void**)&csr,    g_csr);
    cudaGetSymbolAddress((void**)&invdeg, g_invdeg);
    cudaGetSymbolAddress((void**)&agg,    g_agg);
    cudaGetSymbolAddress((void**)&h,      g_h);

    const int nb_nodes = (N + 255) / 256;
    const int nb_edges = (E + 255) / 256;
    const int nb_agg   = (int)(((long long)N * 32 + 255) / 256);
    const int nb_layer = (N + 31) / 32;

    // --- CSR build (per launch; graph-capturable, deterministic structure) ---
    zero_int_kernel<<<nb_nodes, 256>>>(deg_i, N);
    zero_int_kernel<<<nb_nodes, 256>>>(fill, N);
    deg_kernel<<<nb_edges, 256>>>(dst, deg_i, E);
    invdeg_kernel<<<nb_nodes, 256>>>(deg_i, invdeg, N);
    scan_kernel<<<1, 1024>>>(deg_i, rowptr, N);
    fill_csr_kernel<<<nb_edges, 256>>>(src, dst, rowptr, fill, csr, E);

    // --- Layer 1: x -> h ---
    agg_kernel<<<nb_agg, 256>>>(x, rowptr, csr, invdeg, agg, N);
    layer_kernel<128, true><<<nb_layer, 256>>>(x, agg, Ws1, b1, Wn1, h, N);

    // --- Layer 2: h -> h (in-place safe: block stages its rows to smem first) ---
    agg_kernel<<<nb_agg, 256>>>(h, rowptr, csr, invdeg, agg, N);
    layer_kernel<128, true><<<nb_layer, 256>>>(h, agg, Ws2, b2, Wn2, h, N);

    // --- Layer 3: h -> out (mean_agg commutes with the linear map) ---
    agg_kernel<<<nb_agg, 256>>>(h, rowptr, csr, invdeg, agg, N);
    layer_kernel<64, false><<<nb_layer, 256>>>(h, agg, Ws3, b3, Wn3, out, N);
}

// round 4
// speedup vs baseline: 2.6095x; 1.1641x over previous
#include <cuda_runtime.h>
#include <cuda_bf16.h>
#include <cstdint>

#define DIM 128
#define NODES_MAX 50048
#define EDGES_MAX 800000

typedef __nv_bfloat16 bf16;
typedef __nv_bfloat162 bf162;

// ---------------- device scratch (allocation-free rule) ----------------
__device__ int   g_deg_i[NODES_MAX];
__device__ int   g_fill[NODES_MAX];
__device__ int   g_rowptr[NODES_MAX + 1];
__device__ int   g_csr[EDGES_MAX];
__device__ float g_invdeg[NODES_MAX];
__device__ __align__(16) float g_h[(size_t)NODES_MAX * DIM];   // fp32 activations (agg input)
__device__ __align__(16) bf16  g_xh[(size_t)NODES_MAX * DIM];  // split-bf16 GEMM inputs
__device__ __align__(16) bf16  g_xl[(size_t)NODES_MAX * DIM];
__device__ __align__(16) bf16  g_aggh[(size_t)NODES_MAX * DIM];
__device__ __align__(16) bf16  g_aggl[(size_t)NODES_MAX * DIM];
__device__ __align__(16) bf16  g_hh[(size_t)NODES_MAX * DIM];
__device__ __align__(16) bf16  g_hl[(size_t)NODES_MAX * DIM];
__device__ __align__(16) bf16  g_wth[6 * 16384];               // transposed [N][K] weight hi
__device__ __align__(16) bf16  g_wtl[6 * 16384];               // lo parts

// ---------------- PTX helpers (sm_80-baseline features only) ----------------
__device__ __forceinline__ uint32_t smem_to_u32(const void* p) {
    uint32_t a;
    asm("{ .reg .u64 t; cvta.to.shared.u64 t, %1; cvt.u32.u64 %0, t; }" : "=r"(a) : "l"(p));
    return a;
}
__device__ __forceinline__ void ldsm_x4(uint32_t* r, uint32_t addr) {
    asm volatile("ldmatrix.sync.aligned.m8n8.x4.shared.b16 {%0,%1,%2,%3}, [%4];"
                 : "=r"(r[0]), "=r"(r[1]), "=r"(r[2]), "=r"(r[3]) : "r"(addr));
}
__device__ __forceinline__ void mma_bf16(float* d, const uint32_t* a, const uint32_t* b) {
    asm volatile(
        "mma.sync.aligned.m16n8k16.row.col.f32.bf16.bf16.f32 "
        "{%0,%1,%2,%3}, {%4,%5,%6,%7}, {%8,%9}, {%0,%1,%2,%3};"
        : "+f"(d[0]), "+f"(d[1]), "+f"(d[2]), "+f"(d[3])
        : "r"(a[0]), "r"(a[1]), "r"(a[2]), "r"(a[3]), "r"(b[0]), "r"(b[1]));
}

// ---------------- CSR build ----------------
__global__ void zero_int_kernel(int* __restrict__ p, int n) {
    int i = blockIdx.x * blockDim.x + threadIdx.x;
    if (i < n) p[i] = 0;
}
__global__ void deg_kernel(const int* __restrict__ dst, int* __restrict__ deg, int E) {
    int e = blockIdx.x * blockDim.x + threadIdx.x;
    if (e < E) atomicAdd(&deg[dst[e]], 1);
}
__global__ void invdeg_kernel(const int* __restrict__ deg, float* __restrict__ inv, int n) {
    int i = blockIdx.x * blockDim.x + threadIdx.x;
    if (i < n) inv[i] = 1.0f / (float)max(deg[i], 1);
}
// thread-coarsened single-block exclusive scan
__global__ void __launch_bounds__(1024)
scan_kernel(const int* __restrict__ cnt, int* __restrict__ rowptr, int n) {
    __shared__ int wsum[32];
    const int tid = threadIdx.x;
    const int CH = (n + 1023) / 1024;
    const int base = tid * CH;
    int s = 0;
    for (int j = 0; j < CH; ++j) { int i = base + j; if (i < n) s += __ldg(cnt + i); }
    int v = s;
#pragma unroll
    for (int o = 1; o < 32; o <<= 1) { int u = __shfl_up_sync(~0u, v, o); if ((tid & 31) >= o) v += u; }
    if ((tid & 31) == 31) wsum[tid >> 5] = v;
    __syncthreads();
    if (tid < 32) {
        int w = wsum[tid];
#pragma unroll
        for (int o = 1; o < 32; o <<= 1) { int u = __shfl_up_sync(~0u, w, o); if (tid >= o) w += u; }
        wsum[tid] = w;
    }
    __syncthreads();
    int run = (v - s) + ((tid >= 32) ? wsum[(tid >> 5) - 1] : 0);
    for (int j = 0; j < CH; ++j) {
        int i = base + j;
        if (i < n) { run += __ldg(cnt + i); rowptr[i + 1] = run; }
    }
    if (tid == 0) rowptr[0] = 0;
}
__global__ void fill_csr_kernel(const int* __restrict__ src, const int* __restrict__ dst,
                                const int* __restrict__ rowptr, int* __restrict__ fill,
                                int* __restrict__ csr, int E) {
    int e = blockIdx.x * blockDim.x + threadIdx.x;
    if (e < E) {
        int d = dst[e];
        int pos = rowptr[d] + atomicAdd(&fill[d], 1);
        csr[pos] = src[e];
    }
}

// ---------------- split conversions ----------------
__device__ __forceinline__ void split2(float v0, float v1, bf162& hi, bf162& lo) {
    bf16 h0 = __float2bfloat16(v0), h1 = __float2bfloat16(v1);
    bf16 l0 = __float2bfloat16(v0 - __bfloat162float(h0));
    bf16 l1 = __float2bfloat16(v1 - __bfloat162float(h1));
    hi = __halves2bfloat162(h0, h1);
    lo = __halves2bfloat162(l0, l1);
}
__global__ void split_kernel(const float* __restrict__ x, bf16* __restrict__ h,
                             bf16* __restrict__ l, int n2) {
    int i = blockIdx.x * blockDim.x + threadIdx.x;
    if (i < n2) {
        float2 v = reinterpret_cast<const float2*>(x)[i];
        bf162 hi, lo;
        split2(v.x, v.y, hi, lo);
        reinterpret_cast<bf162*>(h)[i] = hi;
        reinterpret_cast<bf162*>(l)[i] = lo;
    }
}
// weights: transpose to [N][K] and split; slots of 16384 elems each.
__global__ void wsplit_kernel(const float* W1s, const float* W1n, const float* W2s,
                              const float* W2n, const float* W3s, const float* W3n,
                              bf16* __restrict__ th, bf16* __restrict__ tl) {
    int i = blockIdx.x * blockDim.x + threadIdx.x;
    int m, off;
    if (i < 4 * 16384) { m = i / 16384; off = i % 16384; }
    else {
        int j = i - 4 * 16384;
        if (j >= 2 * 8192) return;
        m = 4 + j / 8192; off = j % 8192;
    }
    const float* src = (m == 0) ? W1s : (m == 1) ? W1n : (m == 2) ? W2s
                     : (m == 3) ? W2n : (m == 4) ? W3s : W3n;
    int Ncols = (m < 4) ? 128 : 64;
    int nn = off / 128, kk = off % 128;
    float v = src[kk * Ncols + nn];
    bf16 h = __float2bfloat16(v);
    th[m * 16384 + off] = h;
    tl[m * 16384 + off] = __float2bfloat16(v - __bfloat162float(h));
}

// ---------------- atomic-free mean aggregation (fp32 gather -> split bf16 out) ----------------
__global__ void __launch_bounds__(256)
agg_kernel(const float* __restrict__ feat, const int* __restrict__ rowptr,
           const int* __restrict__ csr, const float* __restrict__ invdeg,
           bf16* __restrict__ aggh, bf16* __restrict__ aggl, int n) {
    long long t = (long long)blockIdx.x * blockDim.x + threadIdx.x;
    int v = (int)(t >> 5);
    if (v >= n) return;
    int lane = (int)(t & 31);

    int beg = __ldg(rowptr + v);
    int end = __ldg(rowptr + v + 1);

    float ax = 0.f, ay = 0.f, az = 0.f, aw = 0.f;
    int i = beg;
    for (; i + 4 <= end; i += 4) {
        int s0 = __ldg(csr + i + 0);
        int s1 = __ldg(csr + i + 1);
        int s2 = __ldg(csr + i + 2);
        int s3 = __ldg(csr + i + 3);
        float4 f0 = *reinterpret_cast<const float4*>(feat + (size_t)s0 * DIM + lane * 4);
        float4 f1 = *reinterpret_cast<const float4*>(feat + (size_t)s1 * DIM + lane * 4);
        float4 f2 = *reinterpret_cast<const float4*>(feat + (size_t)s2 * DIM + lane * 4);
        float4 f3 = *reinterpret_cast<const float4*>(feat + (size_t)s3 * DIM + lane * 4);
        ax += (f0.x + f1.x) + (f2.x + f3.x);
        ay += (f0.y + f1.y) + (f2.y + f3.y);
        az += (f0.z + f1.z) + (f2.z + f3.z);
        aw += (f0.w + f1.w) + (f2.w + f3.w);
    }
    for (; i < end; ++i) {
        int s0 = __ldg(csr + i);
        float4 f0 = *reinterpret_cast<const float4*>(feat + (size_t)s0 * DIM + lane * 4);
        ax += f0.x; ay += f0.y; az += f0.z; aw += f0.w;
    }
    float sc = __ldg(invdeg + v);
    bf162 h01, l01, h23, l23;
    split2(ax * sc, ay * sc, h01, l01);
    split2(az * sc, aw * sc, h23, l23);
    reinterpret_cast<bf162*>(aggh + (size_t)v * DIM)[lane * 2 + 0] = h01;
    reinterpret_cast<bf162*>(aggh + (size_t)v * DIM)[lane * 2 + 1] = h23;
    reinterpret_cast<bf162*>(aggl + (size_t)v * DIM)[lane * 2 + 0] = l01;
    reinterpret_cast<bf162*>(aggl + (size_t)v * DIM)[lane * 2 + 1] = l23;
}

// ---------------- HMMA (mma.sync) fused SAGE layer ----------------
// smem tiles: rows x 128 bf16, row stride 256B, 16B-chunk XOR swizzle (conflict-free ldmatrix).
__device__ __forceinline__ void load_swz(const bf16* __restrict__ g, char* __restrict__ s,
                                         int rows, int valid, int t, int nthr) {
    for (int i = t; i < rows * 16; i += nthr) {
        int row = i >> 4, c = i & 15;
        uint4 v = make_uint4(0u, 0u, 0u, 0u);
        if (row < valid) v = *reinterpret_cast<const uint4*>(g + (size_t)row * 128 + c * 8);
        *reinterpret_cast<uint4*>(s + (size_t)row * 256 + ((c ^ (row & 7)) << 4)) = v;
    }
}

// Persistent: weights (Ws/Wn hi+lo, [N][K]) resident in smem; loop over 64-row act tiles.
// 8 warps: warp w -> rows (w&3)*16.., n-half (w>>2)*(NOUT/2)..
template <int NOUT, bool RELU_SPLIT>
__global__ void __launch_bounds__(256, 1)
gemm_kernel(const bf16* __restrict__ xh, const bf16* __restrict__ xl,
            const bf16* __restrict__ gh, const bf16* __restrict__ gl,
            const bf16* __restrict__ wsh, const bf16* __restrict__ wsl,
            const bf16* __restrict__ wnh, const bf16* __restrict__ wnl,
            const float* __restrict__ bias, float* __restrict__ outf,
            bf16* __restrict__ oh, bf16* __restrict__ ol, int n, int ntiles) {
    extern __shared__ char smem[];
    constexpr int NB = NOUT * 256;       // bytes per weight tile
    constexpr int SB = 65536;            // weights after 4 x 16KB act tiles
    const uint32_t sb = smem_to_u32(smem);
    const int t = threadIdx.x;
    const int lane = t & 31, wid = t >> 5;

    // weights: load once per CTA
    load_swz(wsh, smem + SB,          NOUT, NOUT, t, 256);
    load_swz(wsl, smem + SB + NB,     NOUT, NOUT, t, 256);
    load_swz(wnh, smem + SB + 2 * NB, NOUT, NOUT, t, 256);
    load_swz(wnl, smem + SB + 3 * NB, NOUT, NOUT, t, 256);

    // ldmatrix lane addressing (A: 16x16 frag; B: two 8-col tiles per x4)
    const int arow  = (wid & 3) * 16 + (lane & 15);
    const int akh   = lane >> 4;                       // k-half for A
    const int n_off = (wid >> 2) * (NOUT / 2);
    const int browl = ((lane >> 4) << 3) + (lane & 7); // n-row within 16-wide pair
    const int bkh   = (lane >> 3) & 1;                 // k-half for B

    for (int tile = blockIdx.x; tile < ntiles; tile += gridDim.x) {
        const int row0 = tile * 64;
        const int valid = min(64, n - row0);
        __syncthreads();   // previous iter's ldsm done before act overwrite (covers wt stores on iter 0)
        load_swz(xh + (size_t)row0 * 128, smem + 0,     64, valid, t, 256);
        load_swz(xl + (size_t)row0 * 128, smem + 16384, 64, valid, t, 256);
        load_swz(gh + (size_t)row0 * 128, smem + 32768, 64, valid, t, 256);
        load_swz(gl + (size_t)row0 * 128, smem + 49152, 64, valid, t, 256);
        __syncthreads();

        float acc[NOUT / 16][4];
#pragma unroll
        for (int q = 0; q < NOUT / 16; ++q) { acc[q][0] = acc[q][1] = acc[q][2] = acc[q][3] = 0.f; }

#pragma unroll
        for (int ks = 0; ks < 8; ++ks) {
            uint32_t ac   = (uint32_t)((2 * ks + akh) ^ (arow & 7));
            uint32_t aoff = (uint32_t)arow * 256u + (ac << 4);
            uint32_t Ah[4], Al[4], Gh[4], Gl[4];
            ldsm_x4(Ah, sb + aoff);
            ldsm_x4(Al, sb + 16384u + aoff);
            ldsm_x4(Gh, sb + 32768u + aoff);
            ldsm_x4(Gl, sb + 49152u + aoff);
#pragma unroll
            for (int np = 0; np < NOUT / 32; ++np) {
                int brow = n_off + np * 16 + browl;
                uint32_t bc   = (uint32_t)((2 * ks + bkh) ^ (brow & 7));
                uint32_t boff = (uint32_t)brow * 256u + (bc << 4);
                uint32_t Bsh[4], Bsl[4], Bnh[4], Bnl[4];
                ldsm_x4(Bsh, sb + (uint32_t)SB + boff);
                ldsm_x4(Bsl, sb + (uint32_t)(SB + NB) + boff);
                ldsm_x4(Bnh, sb + (uint32_t)(SB + 2 * NB) + boff);
                ldsm_x4(Bnl, sb + (uint32_t)(SB + 3 * NB) + boff);
                float* a0 = acc[np * 2];
                float* a1 = acc[np * 2 + 1];
                // D = Ah*Bh + Gh*Bnh + Al*Bh + Gl*Bnh + Ah*Bl + Gh*Bnl (3-term split x2 operands)
                mma_bf16(a0, Ah, Bsh);     mma_bf16(a1, Ah, Bsh + 2);
                mma_bf16(a0, Gh, Bnh);     mma_bf16(a1, Gh, Bnh + 2);
                mma_bf16(a0, Al, Bsh);     mma_bf16(a1, Al, Bsh + 2);
                mma_bf16(a0, Gl, Bnh);     mma_bf16(a1, Gl, Bnh + 2);
                mma_bf16(a0, Ah, Bsl);     mma_bf16(a1, Ah, Bsl + 2);
                mma_bf16(a0, Gh, Bnl);     mma_bf16(a1, Gh, Bnl + 2);
            }
        }

        // epilogue: bias + (ReLU + bf16 hi/lo re-split) + fp32 store
        const int r0 = row0 + (wid & 3) * 16 + (lane >> 2);
        const int r1 = r0 + 8;
#pragma unroll
        for (int nt = 0; nt < NOUT / 16; ++nt) {
            int c = n_off + nt * 8 + (lane & 3) * 2;
            float b0 = __ldg(bias + c), b1 = __ldg(bias + c + 1);
            float v0 = acc[nt][0] + b0, v1 = acc[nt][1] + b1;
            float v2 = acc[nt][2] + b0, v3 = acc[nt][3] + b1;
            if (RELU_SPLIT) {
                v0 = fmaxf(v0, 0.f); v1 = fmaxf(v1, 0.f);
                v2 = fmaxf(v2, 0.f); v3 = fmaxf(v3, 0.f);
            }
            if (r0 < n) {
                *reinterpret_cast<float2*>(outf + (size_t)r0 * NOUT + c) = make_float2(v0, v1);
                if (RELU_SPLIT) {
                    bf162 hi, lo;
                    split2(v0, v1, hi, lo);
                    *reinterpret_cast<bf162*>(oh + (size_t)r0 * NOUT + c) = hi;
                    *reinterpret_cast<bf162*>(ol + (size_t)r0 * NOUT + c) = lo;
                }
            }
            if (r1 < n) {
                *reinterpret_cast<float2*>(outf + (size_t)r1 * NOUT + c) = make_float2(v2, v3);
                if (RELU_SPLIT) {
                    bf162 hi, lo;
                    split2(v2, v3, hi, lo);
                    *reinterpret_cast<bf162*>(oh + (size_t)r1 * NOUT + c) = hi;
                    *reinterpret_cast<bf162*>(ol + (size_t)r1 * NOUT + c) = lo;
                }
            }
        }
    }
}

// ---------------- launch ----------------
extern "C" void kernel_launch(void* const* d_in, const int* in_sizes, int n_in,
                              void* d_out, int out_size) {
    const float* x   = (const float*)d_in[0];
    const int*   src = (const int*)d_in[1];
    const int*   dst = (const int*)d_in[2];
    const float* Ws1 = (const float*)d_in[3];
    const float* b1  = (const float*)d_in[4];
    const float* Wn1 = (const float*)d_in[5];
    const float* Ws2 = (const float*)d_in[6];
    const float* b2  = (const float*)d_in[7];
    const float* Wn2 = (const float*)d_in[8];
    const float* Ws3 = (const float*)d_in[9];
    const float* b3  = (const float*)d_in[10];
    const float* Wn3 = (const float*)d_in[11];

    const int N = in_sizes[0] / DIM;
    const int E = in_sizes[1];
    float* out = (float*)d_out;

    int *deg_i, *fill, *rowptr, *csr;
    float *invdeg, *h;
    bf16 *xh, *xl, *aggh, *aggl, *hh, *hl, *wth, *wtl;
    cudaGetSymbolAddress((void**)&deg_i,  g_deg_i);
    cudaGetSymbolAddress((void**)&fill,   g_fill);
    cudaGetSymbolAddress((void**)&rowptr, g_rowptr);
    cudaGetSymbolAddress((void**)&csr,    g_csr);
    cudaGetSymbolAddress((void**)&invdeg, g_invdeg);
    cudaGetSymbolAddress((void**)&h,      g_h);
    cudaGetSymbolAddress((void**)&xh,     g_xh);
    cudaGetSymbolAddress((void**)&xl,     g_xl);
    cudaGetSymbolAddress((void**)&aggh,   g_aggh);
    cudaGetSymbolAddress((void**)&aggl,   g_aggl);
    cudaGetSymbolAddress((void**)&hh,     g_hh);
    cudaGetSymbolAddress((void**)&hl,     g_hl);
    cudaGetSymbolAddress((void**)&wth,    g_wth);
    cudaGetSymbolAddress((void**)&wtl,    g_wtl);

    // idempotent, host-side config (not a captured op)
    cudaFuncSetAttribute(gemm_kernel<128, true>,
                         cudaFuncAttributeMaxDynamicSharedMemorySize, 65536 + 4 * 128 * 256);
    cudaFuncSetAttribute(gemm_kernel<64, false>,
                         cudaFuncAttributeMaxDynamicSharedMemorySize, 65536 + 4 * 64 * 256);

    const int nb_nodes = (N + 255) / 256;
    const int nb_edges = (E + 255) / 256;
    const int nb_agg   = (int)(((long long)N * 32 + 255) / 256);
    const int ntiles   = (N + 63) / 64;
    const int GRID     = 152;                   // GB300 SM count, persistent CTAs
    const int SM128    = 65536 + 4 * 128 * 256; // 196608 B
    const int SM64     = 65536 + 4 * 64 * 256;  // 131072 B

    // --- CSR build ---
    zero_int_kernel<<<nb_nodes, 256>>>(deg_i, N);
    zero_int_kernel<<<nb_nodes, 256>>>(fill, N);
    deg_kernel<<<nb_edges, 256>>>(dst, deg_i, E);
    invdeg_kernel<<<nb_nodes, 256>>>(deg_i, invdeg, N);
    scan_kernel<<<1, 1024>>>(deg_i, rowptr, N);
    fill_csr_kernel<<<nb_edges, 256>>>(src, dst, rowptr, fill, csr, E);

    // --- input/weight splits ---
    split_kernel<<<(N * DIM / 2 + 255) / 256, 256>>>(x, xh, xl, N * DIM / 2);
    wsplit_kernel<<<(81920 + 255) / 256, 256>>>(Ws1, Wn1, Ws2, Wn2, Ws3, Wn3, wth, wtl);

    // --- Layer 1: x -> h ---
    agg_kernel<<<nb_agg, 256>>>(x, rowptr, csr, invdeg, aggh, aggl, N);
    gemm_kernel<128, true><<<GRID, 256, SM128>>>(
        xh, xl, aggh, aggl,
        wth + 0 * 16384, wtl + 0 * 16384, wth + 1 * 16384, wtl + 1 * 16384,
        b1, h, hh, hl, N, ntiles);

    // --- Layer 2: h -> h (blocks read only their own rows; write after load) ---
    agg_kernel<<<nb_agg, 256>>>(h, rowptr, csr, invdeg, aggh, aggl, N);
    gemm_kernel<128, true><<<GRID, 256, SM128>>>(
        hh, hl, aggh, aggl,
        wth + 2 * 16384, wtl + 2 * 16384, wth + 3 * 16384, wtl + 3 * 16384,
        b2, h, hh, hl, N, ntiles);

    // --- Layer 3: h -> out (mean_agg commutes with the linear map) ---
    agg_kernel<<<nb_agg, 256>>>(h, rowptr, csr, invdeg, aggh, aggl, N);
    gemm_kernel<64, false><<<GRID, 256, SM64>>>(
        hh, hl, aggh, aggl,
        wth + 4 * 16384, wtl + 4 * 16384, wth + 5 * 16384, wtl + 5 * 16384,
        b3, out, nullptr, nullptr, N, ntiles);
}

// round 5
// speedup vs baseline: 3.2842x; 1.2586x over previous
#include <cuda_runtime.h>
#include <cuda_bf16.h>
#include <cstdint>

#define DIM 128
#define NODES_MAX 50048
#define EDGES_MAX 800000

typedef __nv_bfloat16 bf16;
typedef __nv_bfloat162 bf162;

// ---------------- device scratch (allocation-free rule) ----------------
__device__ int   g_deg_i[NODES_MAX];
__device__ int   g_rowptr[NODES_MAX + 1];
__device__ int   g_csr[EDGES_MAX];
__device__ float g_invdeg[NODES_MAX];
__device__ __align__(16) float g_h[(size_t)NODES_MAX * DIM];   // fp32 activations (agg input)
__device__ __align__(16) bf16  g_xh[(size_t)NODES_MAX * DIM];  // split-bf16 GEMM inputs
__device__ __align__(16) bf16  g_xl[(size_t)NODES_MAX * DIM];
__device__ __align__(16) bf16  g_aggh[(size_t)NODES_MAX * DIM];
__device__ __align__(16) bf16  g_aggl[(size_t)NODES_MAX * DIM];
__device__ __align__(16) bf16  g_hh[(size_t)NODES_MAX * DIM];
__device__ __align__(16) bf16  g_hl[(size_t)NODES_MAX * DIM];
__device__ __align__(16) bf16  g_wth[6 * 16384];               // transposed [N][K] weight hi
__device__ __align__(16) bf16  g_wtl[6 * 16384];               // lo parts

// ---------------- PTX helpers (sm_80-baseline features only) ----------------
__device__ __forceinline__ uint32_t smem_to_u32(const void* p) {
    uint32_t a;
    asm("{ .reg .u64 t; cvta.to.shared.u64 t, %1; cvt.u32.u64 %0, t; }" : "=r"(a) : "l"(p));
    return a;
}
__device__ __forceinline__ void ldsm_x4(uint32_t* r, uint32_t addr) {
    asm volatile("ldmatrix.sync.aligned.m8n8.x4.shared.b16 {%0,%1,%2,%3}, [%4];"
                 : "=r"(r[0]), "=r"(r[1]), "=r"(r[2]), "=r"(r[3]) : "r"(addr));
}
__device__ __forceinline__ void mma_bf16(float* d, const uint32_t* a, const uint32_t* b) {
    asm volatile(
        "mma.sync.aligned.m16n8k16.row.col.f32.bf16.bf16.f32 "
        "{%0,%1,%2,%3}, {%4,%5,%6,%7}, {%8,%9}, {%0,%1,%2,%3};"
        : "+f"(d[0]), "+f"(d[1]), "+f"(d[2]), "+f"(d[3])
        : "r"(a[0]), "r"(a[1]), "r"(a[2]), "r"(a[3]), "r"(b[0]), "r"(b[1]));
}
__device__ __forceinline__ void cp16(uint32_t d, const void* g) {
    asm volatile("cp.async.cg.shared.global [%0], [%1], 16;" :: "r"(d), "l"(g));
}
__device__ __forceinline__ void zero16(uint32_t d) {
    asm volatile("st.shared.v4.b32 [%0], {%1,%1,%1,%1};" :: "r"(d), "r"(0u));
}
#define CP_COMMIT() asm volatile("cp.async.commit_group;" ::: "memory")
#define CP_WAIT1()  asm volatile("cp.async.wait_group 1;" ::: "memory")
#define CP_WAIT0()  asm volatile("cp.async.wait_group 0;" ::: "memory")

// ---------------- CSR build ----------------
__global__ void zero_int_kernel(int* __restrict__ p, int n) {
    int i = blockIdx.x * blockDim.x + threadIdx.x;
    if (i < n) p[i] = 0;
}
__global__ void deg_kernel(const int* __restrict__ dst, int* __restrict__ deg, int E) {
    int e = blockIdx.x * blockDim.x + threadIdx.x;
    if (e < E) atomicAdd(&deg[dst[e]], 1);
}
// thread-coarsened single-block exclusive scan; also emits invdeg
__global__ void __launch_bounds__(1024)
scan_kernel(const int* __restrict__ cnt, int* __restrict__ rowptr,
            float* __restrict__ inv, int n) {
    __shared__ int wsum[32];
    const int tid = threadIdx.x;
    const int CH = (n + 1023) / 1024;
    const int base = tid * CH;
    int s = 0;
    for (int j = 0; j < CH; ++j) { int i = base + j; if (i < n) s += __ldg(cnt + i); }
    int v = s;
#pragma unroll
    for (int o = 1; o < 32; o <<= 1) { int u = __shfl_up_sync(~0u, v, o); if ((tid & 31) >= o) v += u; }
    if ((tid & 31) == 31) wsum[tid >> 5] = v;
    __syncthreads();
    if (tid < 32) {
        int w = wsum[tid];
#pragma unroll
        for (int o = 1; o < 32; o <<= 1) { int u = __shfl_up_sync(~0u, w, o); if (tid >= o) w += u; }
        wsum[tid] = w;
    }
    __syncthreads();
    int run = (v - s) + ((tid >= 32) ? wsum[(tid >> 5) - 1] : 0);
    for (int j = 0; j < CH; ++j) {
        int i = base + j;
        if (i < n) {
            int c = __ldg(cnt + i);
            run += c;
            rowptr[i + 1] = run;
            inv[i] = 1.0f / (float)max(c, 1);
        }
    }
    if (tid == 0) rowptr[0] = 0;
}
// fill via atomic countdown on deg (restores deg to all-zero for the next replay)
__global__ void fill_csr_kernel(const int* __restrict__ src, const int* __restrict__ dst,
                                const int* __restrict__ rowptr, int* __restrict__ deg,
                                int* __restrict__ csr, int E) {
    int e = blockIdx.x * blockDim.x + threadIdx.x;
    if (e < E) {
        int d = dst[e];
        int cnt = atomicAdd(&deg[d], -1);
        csr[rowptr[d] + cnt - 1] = src[e];
    }
}

// ---------------- split conversions ----------------
__device__ __forceinline__ void split2(float v0, float v1, bf162& hi, bf162& lo) {
    bf16 h0 = __float2bfloat16(v0), h1 = __float2bfloat16(v1);
    bf16 l0 = __float2bfloat16(v0 - __bfloat162float(h0));
    bf16 l1 = __float2bfloat16(v1 - __bfloat162float(h1));
    hi = __halves2bfloat162(h0, h1);
    lo = __halves2bfloat162(l0, l1);
}
__global__ void split_kernel(const float* __restrict__ x, bf16* __restrict__ h,
                             bf16* __restrict__ l, int n2) {
    int i = blockIdx.x * blockDim.x + threadIdx.x;
    if (i < n2) {
        float2 v = reinterpret_cast<const float2*>(x)[i];
        bf162 hi, lo;
        split2(v.x, v.y, hi, lo);
        reinterpret_cast<bf162*>(h)[i] = hi;
        reinterpret_cast<bf162*>(l)[i] = lo;
    }
}
__global__ void wsplit_kernel(const float* W1s, const float* W1n, const float* W2s,
                              const float* W2n, const float* W3s, const float* W3n,
                              bf16* __restrict__ th, bf16* __restrict__ tl) {
    int i = blockIdx.x * blockDim.x + threadIdx.x;
    int m, off;
    if (i < 4 * 16384) { m = i / 16384; off = i % 16384; }
    else {
        int j = i - 4 * 16384;
        if (j >= 2 * 8192) return;
        m = 4 + j / 8192; off = j % 8192;
    }
    const float* src = (m == 0) ? W1s : (m == 1) ? W1n : (m == 2) ? W2s
                     : (m == 3) ? W2n : (m == 4) ? W3s : W3n;
    int Ncols = (m < 4) ? 128 : 64;
    int nn = off / 128, kk = off % 128;
    float v = src[kk * Ncols + nn];
    bf16 h = __float2bfloat16(v);
    th[m * 16384 + off] = h;
    tl[m * 16384 + off] = __float2bfloat16(v - __bfloat162float(h));
}

// ---------------- atomic-free mean aggregation (fp32 gather -> split bf16 out) ----------------
__global__ void __launch_bounds__(256)
agg_kernel(const float* __restrict__ feat, const int* __restrict__ rowptr,
           const int* __restrict__ csr, const float* __restrict__ invdeg,
           bf16* __restrict__ aggh, bf16* __restrict__ aggl, int n) {
    long long t = (long long)blockIdx.x * blockDim.x + threadIdx.x;
    int v = (int)(t >> 5);
    if (v >= n) return;
    int lane = (int)(t & 31);

    int beg = __ldg(rowptr + v);
    int end = __ldg(rowptr + v + 1);

    float ax = 0.f, ay = 0.f, az = 0.f, aw = 0.f;
    int i = beg;
    for (; i + 4 <= end; i += 4) {
        int s0 = __ldg(csr + i + 0);
        int s1 = __ldg(csr + i + 1);
        int s2 = __ldg(csr + i + 2);
        int s3 = __ldg(csr + i + 3);
        float4 f0 = *reinterpret_cast<const float4*>(feat + (size_t)s0 * DIM + lane * 4);
        float4 f1 = *reinterpret_cast<const float4*>(feat + (size_t)s1 * DIM + lane * 4);
        float4 f2 = *reinterpret_cast<const float4*>(feat + (size_t)s2 * DIM + lane * 4);
        float4 f3 = *reinterpret_cast<const float4*>(feat + (size_t)s3 * DIM + lane * 4);
        ax += (f0.x + f1.x) + (f2.x + f3.x);
        ay += (f0.y + f1.y) + (f2.y + f3.y);
        az += (f0.z + f1.z) + (f2.z + f3.z);
        aw += (f0.w + f1.w) + (f2.w + f3.w);
    }
    for (; i < end; ++i) {
        int s0 = __ldg(csr + i);
        float4 f0 = *reinterpret_cast<const float4*>(feat + (size_t)s0 * DIM + lane * 4);
        ax += f0.x; ay += f0.y; az += f0.z; aw += f0.w;
    }
    float sc = __ldg(invdeg + v);
    bf162 h01, l01, h23, l23;
    split2(ax * sc, ay * sc, h01, l01);
    split2(az * sc, aw * sc, h23, l23);
    reinterpret_cast<bf162*>(aggh + (size_t)v * DIM)[lane * 2 + 0] = h01;
    reinterpret_cast<bf162*>(aggh + (size_t)v * DIM)[lane * 2 + 1] = h23;
    reinterpret_cast<bf162*>(aggl + (size_t)v * DIM)[lane * 2 + 0] = l01;
    reinterpret_cast<bf162*>(aggl + (size_t)v * DIM)[lane * 2 + 1] = l23;
}

// ---------------- HMMA fused SAGE layer: persistent, cp.async double-buffered ----------------
// smem: [stage0: 4 x 8KB act tiles][stage1: same] @0/32768; weights @65536 (4 x NOUT*256B).
// Tiles: rows x 128 bf16, row stride 256B, 16B-chunk XOR swizzle (conflict-free ldsm).
__device__ __forceinline__ void load_swz(const bf16* __restrict__ g, char* __restrict__ s,
                                         int rows, int t) {
    for (int i = t; i < rows * 16; i += 256) {
        int row = i >> 4, c = i & 15;
        uint4 v = *reinterpret_cast<const uint4*>(g + (size_t)row * 128 + c * 8);
        *reinterpret_cast<uint4*>(s + (size_t)row * 256 + ((c ^ (row & 7)) << 4)) = v;
    }
}
__device__ __forceinline__ void issue_tile(const bf16* __restrict__ xh, const bf16* __restrict__ xl,
                                           const bf16* __restrict__ gh, const bf16* __restrict__ gl,
                                           int row0, int n, uint32_t stage, int t) {
    int valid = min(32, n - row0);
    for (int i = t; i < 512; i += 256) {
        int row = i >> 4, c = i & 15;
        uint32_t off = (uint32_t)row * 256u + (uint32_t)((c ^ (row & 7)) << 4);
        size_t goff = (size_t)(row0 + row) * 128 + c * 8;
        if (row < valid) {
            cp16(stage + off,          xh + goff);
            cp16(stage + 8192u + off,  xl + goff);
            cp16(stage + 16384u + off, gh + goff);
            cp16(stage + 24576u + off, gl + goff);
        } else {
            zero16(stage + off);          zero16(stage + 8192u + off);
            zero16(stage + 16384u + off); zero16(stage + 24576u + off);
        }
    }
}

template <int NOUT, bool RELU_SPLIT>
__global__ void __launch_bounds__(256, 1)
gemm_kernel(const bf16* __restrict__ xh, const bf16* __restrict__ xl,
            const bf16* __restrict__ gh, const bf16* __restrict__ gl,
            const bf16* __restrict__ wsh, const bf16* __restrict__ wsl,
            const bf16* __restrict__ wnh, const bf16* __restrict__ wnl,
            const float* __restrict__ bias, float* __restrict__ outf,
            bf16* __restrict__ oh, bf16* __restrict__ ol, int n, int ntiles) {
    extern __shared__ char smem[];
    constexpr int NB = NOUT * 256;   // bytes per weight tile
    constexpr int WBASE = 65536;
    constexpr int NPW = NOUT / 4;    // cols per warp
    constexpr int NT = NPW / 8;      // 8-col acc tiles per warp
    const uint32_t sb = smem_to_u32(smem);
    const uint32_t wb = sb + WBASE;
    const int t = threadIdx.x, lane = t & 31, wid = t >> 5;

    // weights resident (loaded once per CTA)
    load_swz(wsh, smem + WBASE,          NOUT, t);
    load_swz(wsl, smem + WBASE + NB,     NOUT, t);
    load_swz(wnh, smem + WBASE + 2 * NB, NOUT, t);
    load_swz(wnl, smem + WBASE + 3 * NB, NOUT, t);

    // warp layout: rows {0,16} by wid&1; n-quarter by wid>>1
    const int rhalf = (wid & 1) * 16;
    const int n0 = (wid >> 1) * NPW;
    const int arowl = rhalf + (lane & 15);
    const int akh = lane >> 4;
    const int browl = ((lane >> 4) << 3) + (lane & 7);
    const int bkh = (lane >> 3) & 1;

    // hoist bias
    float breg[NT][2];
#pragma unroll
    for (int nt = 0; nt < NT; ++nt) {
        int c = n0 + nt * 8 + (lane & 3) * 2;
        breg[nt][0] = __ldg(bias + c);
        breg[nt][1] = __ldg(bias + c + 1);
    }

    int tile = blockIdx.x, buf = 0;
    issue_tile(xh, xl, gh, gl, tile * 32, n, sb, t);
    CP_COMMIT();

    for (; tile < ntiles; tile += gridDim.x) {
        const int nxt = tile + gridDim.x;
        const bool hn = nxt < ntiles;
        if (hn) {
            issue_tile(xh, xl, gh, gl, nxt * 32, n, sb + (uint32_t)(buf ^ 1) * 32768u, t);
            CP_COMMIT();
            CP_WAIT1();
        } else {
            CP_WAIT0();
        }
        __syncthreads();

        const uint32_t ab = sb + (uint32_t)buf * 32768u;
        float acc[NT][4];
#pragma unroll
        for (int q = 0; q < NT; ++q) { acc[q][0] = acc[q][1] = acc[q][2] = acc[q][3] = 0.f; }

#pragma unroll
        for (int ks = 0; ks < 8; ++ks) {
            uint32_t ac = (uint32_t)((2 * ks + akh) ^ (arowl & 7));
            uint32_t aoff = (uint32_t)arowl * 256u + (ac << 4);
            uint32_t Ah[4], Al[4], Gh[4], Gl[4];
            ldsm_x4(Ah, ab + aoff);
            ldsm_x4(Al, ab + 8192u + aoff);
            ldsm_x4(Gh, ab + 16384u + aoff);
            ldsm_x4(Gl, ab + 24576u + aoff);
#pragma unroll
            for (int np = 0; np < NT / 2; ++np) {
                int brow = n0 + np * 16 + browl;
                uint32_t bc = (uint32_t)((2 * ks + bkh) ^ (brow & 7));
                uint32_t boff = (uint32_t)brow * 256u + (bc << 4);
                uint32_t Bsh[4], Bsl[4], Bnh[4], Bnl[4];
                ldsm_x4(Bsh, wb + boff);
                ldsm_x4(Bsl, wb + (uint32_t)NB + boff);
                ldsm_x4(Bnh, wb + (uint32_t)(2 * NB) + boff);
                ldsm_x4(Bnl, wb + (uint32_t)(3 * NB) + boff);
                float* a0 = acc[np * 2];
                float* a1 = acc[np * 2 + 1];
                // D = (Ah+Al)(Bh+Bl) minus Al*Bl terms, self + neigh
                mma_bf16(a0, Ah, Bsh);  mma_bf16(a1, Ah, Bsh + 2);
                mma_bf16(a0, Gh, Bnh);  mma_bf16(a1, Gh, Bnh + 2);
                mma_bf16(a0, Al, Bsh);  mma_bf16(a1, Al, Bsh + 2);
                mma_bf16(a0, Gl, Bnh);  mma_bf16(a1, Gl, Bnh + 2);
                mma_bf16(a0, Ah, Bsl);  mma_bf16(a1, Ah, Bsl + 2);
                mma_bf16(a0, Gh, Bnl);  mma_bf16(a1, Gh, Bnl + 2);
            }
        }

        // epilogue: bias + (ReLU + bf16 hi/lo re-split) + fp32 store
        const int r0 = tile * 32 + rhalf + (lane >> 2);
        const int r1 = r0 + 8;
#pragma unroll
        for (int nt = 0; nt < NT; ++nt) {
            int c = n0 + nt * 8 + (lane & 3) * 2;
            float v0 = acc[nt][0] + breg[nt][0], v1 = acc[nt][1] + breg[nt][1];
            float v2 = acc[nt][2] + breg[nt][0], v3 = acc[nt][3] + breg[nt][1];
            if (RELU_SPLIT) {
                v0 = fmaxf(v0, 0.f); v1 = fmaxf(v1, 0.f);
                v2 = fmaxf(v2, 0.f); v3 = fmaxf(v3, 0.f);
            }
            if (r0 < n) {
                *reinterpret_cast<float2*>(outf + (size_t)r0 * NOUT + c) = make_float2(v0, v1);
                if (RELU_SPLIT) {
                    bf162 hi, lo;
                    split2(v0, v1, hi, lo);
                    *reinterpret_cast<bf162*>(oh + (size_t)r0 * NOUT + c) = hi;
                    *reinterpret_cast<bf162*>(ol + (size_t)r0 * NOUT + c) = lo;
                }
            }
            if (r1 < n) {
                *reinterpret_cast<float2*>(outf + (size_t)r1 * NOUT + c) = make_float2(v2, v3);
                if (RELU_SPLIT) {
                    bf162 hi, lo;
                    split2(v2, v3, hi, lo);
                    *reinterpret_cast<bf162*>(oh + (size_t)r1 * NOUT + c) = hi;
                    *reinterpret_cast<bf162*>(ol + (size_t)r1 * NOUT + c) = lo;
                }
            }
        }
        __syncthreads();   // all warps done with buf before it is re-filled next iter
        buf ^= 1;
    }
}

// ---------------- launch ----------------
extern "C" void kernel_launch(void* const* d_in, const int* in_sizes, int n_in,
                              void* d_out, int out_size) {
    const float* x   = (const float*)d_in[0];
    const int*   src = (const int*)d_in[1];
    const int*   dst = (const int*)d_in[2];
    const float* Ws1 = (const float*)d_in[3];
    const float* b1  = (const float*)d_in[4];
    const float* Wn1 = (const float*)d_in[5];
    const float* Ws2 = (const float*)d_in[6];
    const float* b2  = (const float*)d_in[7];
    const float* Wn2 = (const float*)d_in[8];
    const float* Ws3 = (const float*)d_in[9];
    const float* b3  = (const float*)d_in[10];
    const float* Wn3 = (const float*)d_in[11];

    const int N = in_sizes[0] / DIM;
    const int E = in_sizes[1];
    float* out = (float*)d_out;

    int *deg_i, *rowptr, *csr;
    float *invdeg, *h;
    bf16 *xh, *xl, *aggh, *aggl, *hh, *hl, *wth, *wtl;
    cudaGetSymbolAddress((void**)&deg_i,  g_deg_i);
    cudaGetSymbolAddress((void**)&rowptr, g_rowptr);
    cudaGetSymbolAddress((void**)&csr,    g_csr);
    cudaGetSymbolAddress((void**)&invdeg, g_invdeg);
    cudaGetSymbolAddress((void**)&h,      g_h);
    cudaGetSymbolAddress((void**)&xh,     g_xh);
    cudaGetSymbolAddress((void**)&xl,     g_xl);
    cudaGetSymbolAddress((void**)&aggh,   g_aggh);
    cudaGetSymbolAddress((void**)&aggl,   g_aggl);
    cudaGetSymbolAddress((void**)&hh,     g_hh);
    cudaGetSymbolAddress((void**)&hl,     g_hl);
    cudaGetSymbolAddress((void**)&wth,    g_wth);
    cudaGetSymbolAddress((void**)&wtl,    g_wtl);

    const int SM128 = 65536 + 4 * 128 * 256;  // 196608 B
    const int SM64  = 65536 + 4 * 64 * 256;   // 131072 B
    cudaFuncSetAttribute(gemm_kernel<128, true>,
                         cudaFuncAttributeMaxDynamicSharedMemorySize, SM128);
    cudaFuncSetAttribute(gemm_kernel<64, false>,
                         cudaFuncAttributeMaxDynamicSharedMemorySize, SM64);

    const int nb_nodes = (N + 255) / 256;
    const int nb_edges = (E + 255) / 256;
    const int nb_agg   = (int)(((long long)N * 32 + 255) / 256);
    const int ntiles   = (N + 31) / 32;
    const int GRID     = 152;

    // --- CSR build ---
    zero_int_kernel<<<nb_nodes, 256>>>(deg_i, N);
    deg_kernel<<<nb_edges, 256>>>(dst, deg_i, E);
    scan_kernel<<<1, 1024>>>(deg_i, rowptr, invdeg, N);
    fill_csr_kernel<<<nb_edges, 256>>>(src, dst, rowptr, deg_i, csr, E);

    // --- input/weight splits ---
    split_kernel<<<(N * DIM / 2 + 255) / 256, 256>>>(x, xh, xl, N * DIM / 2);
    wsplit_kernel<<<(81920 + 255) / 256, 256>>>(Ws1, Wn1, Ws2, Wn2, Ws3, Wn3, wth, wtl);

    // --- Layer 1: x -> h ---
    agg_kernel<<<nb_agg, 256>>>(x, rowptr, csr, invdeg, aggh, aggl, N);
    gemm_kernel<128, true><<<GRID, 256, SM128>>>(
        xh, xl, aggh, aggl,
        wth + 0 * 16384, wtl + 0 * 16384, wth + 1 * 16384, wtl + 1 * 16384,
        b1, h, hh, hl, N, ntiles);

    // --- Layer 2: h -> h ---
    agg_kernel<<<nb_agg, 256>>>(h, rowptr, csr, invdeg, aggh, aggl, N);
    gemm_kernel<128, true><<<GRID, 256, SM128>>>(
        hh, hl, aggh, aggl,
        wth + 2 * 16384, wtl + 2 * 16384, wth + 3 * 16384, wtl + 3 * 16384,
        b2, h, hh, hl, N, ntiles);

    // --- Layer 3: h -> out (mean_agg commutes with the linear map) ---
    agg_kernel<<<nb_agg, 256>>>(h, rowptr, csr, invdeg, aggh, aggl, N);
    gemm_kernel<64, false><<<GRID, 256, SM64>>>(
        hh, hl, aggh, aggl,
        wth + 4 * 16384, wtl + 4 * 16384, wth + 5 * 16384, wtl + 5 * 16384,
        b3, out, nullptr, nullptr, N, ntiles);
}